// round 4
// baseline (speedup 1.0000x reference)
#include <cuda_runtime.h>
#include <float.h>

// Shapes (fixed by the problem): B=32, S=4096, H=1024, K=2
#define B_ 32
#define S_ 4096
#define H_ 1024
#define K_ 2

#define LANES   16                 // feature lanes per block (float4 each)
#define GROUPS  16                 // row groups per block
#define THREADS (LANES*GROUPS)     // 256
#define CHUNK   (LANES*4)          // 64 features per block
#define CHUNKS  (H_/CHUNK)         // 16

__device__ __forceinline__ float4 f4max(float4 a, float4 b) {
    float4 r;
    r.x = fmaxf(a.x, b.x);
    r.y = fmaxf(a.y, b.y);
    r.z = fmaxf(a.z, b.z);
    r.w = fmaxf(a.w, b.w);
    return r;
}

__global__ void __launch_bounds__(THREADS)
span_max_kernel(const float* __restrict__ hs,   // [B, S, H]
                const int* __restrict__ st,     // [B, K] (int32)
                const int* __restrict__ en,     // [B, K]
                const float* __restrict__ me,   // [K, H]
                float* __restrict__ out)        // [B, K*H]
{
    __shared__ float4 part[GROUPS][LANES];

    const int blk   = blockIdx.x;
    const int chunk = blk % CHUNKS;
    const int bk    = blk / CHUNKS;
    const int b     = bk / K_;
    const int k     = bk % K_;

    const int lane = threadIdx.x & (LANES - 1);
    const int g    = threadIdx.x / LANES;

    const int f = chunk * CHUNK + lane * 4;     // feature offset

    const int s_raw = __ldg(&st[b * K_ + k]);
    const int e_raw = __ldg(&en[b * K_ + k]);

    float* op = out + (size_t)b * (K_ * H_) + (size_t)k * H_ + f;

    if (s_raw < 0 || e_raw < 0) {
        // missing: copy missing_embeddings[k]; all threads return (no syncs follow)
        if (g == 0) {
            float4 v = *reinterpret_cast<const float4*>(me + (size_t)k * H_ + f);
            *reinterpret_cast<float4*>(op) = v;
        }
        return;
    }

    // defensive clamps: never index outside [0, S)
    const int s = s_raw < S_ ? s_raw : S_;
    const int e = e_raw < S_ ? e_raw : S_;

    const float* base = hs + ((size_t)b * S_) * H_ + f;

    const float4 NEG = make_float4(-FLT_MAX, -FLT_MAX, -FLT_MAX, -FLT_MAX);

    // up to ceil(63/16)=4 rows per thread, fully peeled into independent
    // predicated loads: one latency wait instead of a serial chain.
    const int r0 = s + g;
    const int r1 = r0 + GROUPS;
    const int r2 = r0 + 2 * GROUPS;
    const int r3 = r0 + 3 * GROUPS;

    float4 a0 = (r0 < e) ? *reinterpret_cast<const float4*>(base + (size_t)r0 * H_) : NEG;
    float4 a1 = (r1 < e) ? *reinterpret_cast<const float4*>(base + (size_t)r1 * H_) : NEG;
    float4 a2 = (r2 < e) ? *reinterpret_cast<const float4*>(base + (size_t)r2 * H_) : NEG;
    float4 a3 = (r3 < e) ? *reinterpret_cast<const float4*>(base + (size_t)r3 * H_) : NEG;
    float4 m = f4max(f4max(a0, a1), f4max(a2, a3));

    // tail safety for spans longer than 4*GROUPS (cannot happen with len<64,
    // but keeps the kernel correct for any input)
    for (int r = r0 + 4 * GROUPS; r < e; r += GROUPS) {
        float4 a = *reinterpret_cast<const float4*>(base + (size_t)r * H_);
        m = f4max(m, a);
    }

    part[g][lane] = m;
    __syncthreads();

    if (g == 0) {
        // 15 independent LDS.128 + fmax tree (compiler unrolls)
        float4 acc = part[0][lane];
        #pragma unroll
        for (int i = 1; i < GROUPS; i++)
            acc = f4max(acc, part[i][lane]);
        *reinterpret_cast<float4*>(op) = acc;
    }
}

extern "C" void kernel_launch(void* const* d_in, const int* in_sizes, int n_in,
                              void* d_out, int out_size) {
    const float* hs  = (const float*)d_in[0];
    const int*   st  = (const int*)d_in[1];
    const int*   en  = (const int*)d_in[2];
    const float* me  = (const float*)d_in[3];
    float*       out = (float*)d_out;

    dim3 grid(B_ * K_ * CHUNKS);   // 1024 blocks — single wave on 148 SMs
    span_max_kernel<<<grid, THREADS>>>(hs, st, en, me, out);
}

// round 5
// speedup vs baseline: 1.0047x; 1.0047x over previous
#include <cuda_runtime.h>
#include <float.h>

// Shapes (fixed by the problem): B=32, S=4096, H=1024, K=2
#define B_ 32
#define S_ 4096
#define H_ 1024
#define K_ 2

#define LANES   64                 // feature lanes per block (float4 each)
#define GROUPS  8                  // row groups per block
#define THREADS (LANES*GROUPS)     // 512
#define CHUNK   (LANES*4)          // 256 features per block
#define CHUNKS  (H_/CHUNK)         // 4

__device__ __forceinline__ float4 f4max(float4 a, float4 b) {
    float4 r;
    r.x = fmaxf(a.x, b.x);
    r.y = fmaxf(a.y, b.y);
    r.z = fmaxf(a.z, b.z);
    r.w = fmaxf(a.w, b.w);
    return r;
}

__global__ void __launch_bounds__(THREADS)
span_max_kernel(const float* __restrict__ hs,   // [B, S, H]
                const int* __restrict__ st,     // [B, K] (int32)
                const int* __restrict__ en,     // [B, K]
                const float* __restrict__ me,   // [K, H]
                float* __restrict__ out)        // [B, K*H]
{
    __shared__ float4 part[GROUPS][LANES];

    const int blk   = blockIdx.x;
    const int chunk = blk % CHUNKS;
    const int bk    = blk / CHUNKS;
    const int b     = bk / K_;
    const int k     = bk % K_;

    const int lane = threadIdx.x & (LANES - 1);
    const int g    = threadIdx.x / LANES;

    const int f = chunk * CHUNK + lane * 4;     // feature offset

    const int s_raw = __ldg(&st[b * K_ + k]);
    const int e_raw = __ldg(&en[b * K_ + k]);

    float* op = out + (size_t)b * (K_ * H_) + (size_t)k * H_ + f;

    if (s_raw < 0 || e_raw < 0) {
        // missing: copy missing_embeddings[k]; all threads return (no syncs follow)
        if (g == 0) {
            float4 v = *reinterpret_cast<const float4*>(me + (size_t)k * H_ + f);
            *reinterpret_cast<float4*>(op) = v;
        }
        return;
    }

    // defensive clamps: keep every generated row index inside [0, S)
    const int s  = s_raw < S_ ? s_raw : (S_ - 1);
    const int e  = e_raw < S_ ? e_raw : S_;
    const int el = e - 1;                        // last valid row (e >= 1 here)

    const float* base = hs + ((size_t)b * S_) * H_ + f;

    // 8 independent, UNPREDICATED loads per thread: row index clamped to the
    // span's last row instead of predicating. Duplicate reads of row el are
    // harmless for max and coalesce onto already-inflight lines.
    // Rows covered: s+g+8j for g in [0,8), j in [0,8) => s .. s+63 (span < 64).
    float4 m;
    {
        int r0 = s + g;
        int r1 = r0 + 1 * GROUPS;
        int r2 = r0 + 2 * GROUPS;
        int r3 = r0 + 3 * GROUPS;
        int r4 = r0 + 4 * GROUPS;
        int r5 = r0 + 5 * GROUPS;
        int r6 = r0 + 6 * GROUPS;
        int r7 = r0 + 7 * GROUPS;
        r0 = r0 < el ? r0 : el;
        r1 = r1 < el ? r1 : el;
        r2 = r2 < el ? r2 : el;
        r3 = r3 < el ? r3 : el;
        r4 = r4 < el ? r4 : el;
        r5 = r5 < el ? r5 : el;
        r6 = r6 < el ? r6 : el;
        r7 = r7 < el ? r7 : el;
        float4 a0 = *reinterpret_cast<const float4*>(base + (size_t)r0 * H_);
        float4 a1 = *reinterpret_cast<const float4*>(base + (size_t)r1 * H_);
        float4 a2 = *reinterpret_cast<const float4*>(base + (size_t)r2 * H_);
        float4 a3 = *reinterpret_cast<const float4*>(base + (size_t)r3 * H_);
        float4 a4 = *reinterpret_cast<const float4*>(base + (size_t)r4 * H_);
        float4 a5 = *reinterpret_cast<const float4*>(base + (size_t)r5 * H_);
        float4 a6 = *reinterpret_cast<const float4*>(base + (size_t)r6 * H_);
        float4 a7 = *reinterpret_cast<const float4*>(base + (size_t)r7 * H_);
        m = f4max(f4max(f4max(a0, a1), f4max(a2, a3)),
                  f4max(f4max(a4, a5), f4max(a6, a7)));
    }

    // generic-safety tail for spans longer than 64 rows (never taken here)
    for (int r = s + g + 8 * GROUPS; r < e; r += GROUPS) {
        float4 a = *reinterpret_cast<const float4*>(base + (size_t)r * H_);
        m = f4max(m, a);
    }

    part[g][lane] = m;
    __syncthreads();

    if (g == 0) {
        float4 acc = part[0][lane];
        #pragma unroll
        for (int i = 1; i < GROUPS; i++)
            acc = f4max(acc, part[i][lane]);
        *reinterpret_cast<float4*>(op) = acc;
    }
}

extern "C" void kernel_launch(void* const* d_in, const int* in_sizes, int n_in,
                              void* d_out, int out_size) {
    const float* hs  = (const float*)d_in[0];
    const int*   st  = (const int*)d_in[1];
    const int*   en  = (const int*)d_in[2];
    const float* me  = (const float*)d_in[3];
    float*       out = (float*)d_out;

    dim3 grid(B_ * K_ * CHUNKS);   // 256 blocks, one wave
    span_max_kernel<<<grid, THREADS>>>(hs, st, en, me, out);
}